// round 6
// baseline (speedup 1.0000x reference)
#include <cuda_runtime.h>

#define NBOX   8192
#define NT     1024
#define EPT    8                 // elements per thread (NBOX/NT)
#define NW32   (NBOX / 32)       // 256 keep words

struct SmemLayout {
    unsigned long long keys[NBOX];   // (conf_bits<<32) | (0xFFFFFFFF - idx), sorted descending
    float4             boxes[NBOX];  // xyxy in sorted order, filled for i < V
    unsigned int       keep32[NW32]; // working survivor bitmask (sorted order)
    unsigned int       final32[NW32];// final kept bitmask per chunk
    float              redbuf[32];
    float              maxv;
    int                V;
};

__device__ __forceinline__ unsigned long long u64max(unsigned long long a, unsigned long long b) { return a > b ? a : b; }
__device__ __forceinline__ unsigned long long u64min(unsigned long long a, unsigned long long b) { return a < b ? a : b; }

// One bitonic stage (k, j) with j <= 128, operating on 8 registers per thread.
// Element e = base + r. Comparator produces DESCENDING order overall.
__device__ __forceinline__ void local_stage(unsigned long long v[EPT], int base, int k, int j)
{
    if (j < EPT) {
        // in-thread pairs (r, r|j), j in {1,2,4}
#pragma unroll
        for (int r = 0; r < EPT; r++) {
            if ((r & j) == 0) {
                int r2 = r | j;
                bool dir = (((base + r) & k) == 0);   // descending block
                unsigned long long a = v[r], b = v[r2];
                bool sw = dir ? (a < b) : (a > b);
                if (sw) { v[r] = b; v[r2] = a; }
            }
        }
    } else {
        // cross-thread within warp: partner lane = lane ^ (j/8)
        int m = j >> 3;
#pragma unroll
        for (int r = 0; r < EPT; r++) {
            unsigned long long p = __shfl_xor_sync(0xFFFFFFFFu, v[r], m);
            int e = base + r;
            bool dir   = ((e & k) == 0);
            bool lower = ((e & j) == 0);
            unsigned long long a = v[r];
            v[r] = (dir == lower) ? u64max(a, p) : u64min(a, p);
        }
    }
}

__device__ __forceinline__ float iou_f(float4 a, float4 b)
{
    float ix1 = fmaxf(a.x, b.x);
    float iy1 = fmaxf(a.y, b.y);
    float ix2 = fminf(a.z, b.z);
    float iy2 = fminf(a.w, b.w);
    float iw  = fmaxf(ix2 - ix1, 0.0f);
    float ih  = fmaxf(iy2 - iy1, 0.0f);
    float inter = iw * ih;
    float areaA = (a.z - a.x) * (a.w - a.y);
    float areaB = (b.z - b.x) * (b.w - b.y);
    float uni   = areaA + areaB - inter;
    return inter / fmaxf(uni, 1e-9f);
}

__global__ void __launch_bounds__(NT, 1)
rtdetr_postprocess_kernel(const float* __restrict__ in, float* __restrict__ out)
{
    extern __shared__ unsigned char smem_raw[];
    SmemLayout* s = reinterpret_cast<SmemLayout*>(smem_raw);
    const int tid  = (int)threadIdx.x;
    const int lane = tid & 31;
    const int base = tid * EPT;          // first owned element index

    if (tid == 0) s->V = 0;

    // ---- 1. load confs (thread-contiguous), warp max ----
    unsigned long long v[EPT];
    float lmax = 0.0f;                   // conf >= 0 for this workload
#pragma unroll
    for (int r = 0; r < EPT; r++) {
        int i = base + r;
        float c = in[i * 5 + 4];
        lmax = fmaxf(lmax, c);
        unsigned int cb = __float_as_uint(c);   // non-negative: bit pattern order-preserving
        v[r] = ((unsigned long long)cb << 32) | (unsigned int)(0xFFFFFFFFu - (unsigned int)i);
    }
#pragma unroll
    for (int o = 16; o > 0; o >>= 1) lmax = fmaxf(lmax, __shfl_xor_sync(0xFFFFFFFFu, lmax, o));
    if (lane == 0) s->redbuf[tid >> 5] = lmax;

    // ---- 2a. bitonic: k = 2..256 entirely in registers/warp ----
    for (int k = 2; k <= 256; k <<= 1)
        for (int j = k >> 1; j >= 1; j >>= 1)
            local_stage(v, base, k, j);

#pragma unroll
    for (int r = 0; r < EPT; r++) s->keys[base + r] = v[r];
    __syncthreads();

    // finish the max reduce (redbuf now visible)
    if (tid < 32) {
        float m = s->redbuf[tid];
#pragma unroll
        for (int o = 16; o > 0; o >>= 1) m = fmaxf(m, __shfl_xor_sync(0xFFFFFFFFu, m, o));
        if (tid == 0) s->maxv = m;
    }

    // ---- 2b. bitonic: k = 512..8192; smem stages for j>=256, register phase for j<=128 ----
    for (int k = 512; k <= NBOX; k <<= 1) {
        for (int j = k >> 1; j >= 256; j >>= 1) {
#pragma unroll
            for (int r = 0; r < EPT; r++) {
                int i = tid + (r << 10);
                int ixj = i ^ j;
                if (ixj > i) {
                    unsigned long long a = s->keys[i];
                    unsigned long long b = s->keys[ixj];
                    bool desc = ((i & k) == 0);
                    if (desc ? (a < b) : (a > b)) { s->keys[i] = b; s->keys[ixj] = a; }
                }
            }
            __syncthreads();
        }
#pragma unroll
        for (int r = 0; r < EPT; r++) v[r] = s->keys[base + r];
        for (int j = 128; j >= 1; j >>= 1) local_stage(v, base, k, j);
#pragma unroll
        for (int r = 0; r < EPT; r++) s->keys[base + r] = v[r];
        __syncthreads();
    }

    // ---- 3. V = number of valid elements (valid is a sorted prefix -> count == boundary) ----
    const float maxv = s->maxv;
    int cnt = 0;
#pragma unroll
    for (int r = 0; r < EPT; r++) {
        float c = __uint_as_float((unsigned int)(v[r] >> 32));
        cnt += ((c / maxv) >= 0.5f) ? 1 : 0;
    }
#pragma unroll
    for (int o = 16; o > 0; o >>= 1) cnt += __shfl_xor_sync(0xFFFFFFFFu, cnt, o);
    if (lane == 0) atomicAdd(&s->V, cnt);
    __syncthreads();
    const int V = s->V;

    // ---- 4. gather xyxy boxes for valid prefix; init working keep mask ----
    for (int i = tid; i < V; i += NT) {
        unsigned int idx = 0xFFFFFFFFu - (unsigned int)(s->keys[i] & 0xFFFFFFFFull);
        const float* p = in + (size_t)idx * 5;
        float cx = p[0], cy = p[1], w = p[2], h = p[3];
        s->boxes[i] = make_float4(cx - w * 0.5f, cy - h * 0.5f,
                                  cx + w * 0.5f, cy + h * 0.5f);
    }
    for (int wI = tid; wI < NW32; wI += NT) {
        int b0 = wI * 32;
        unsigned int word;
        if (V >= b0 + 32)      word = 0xFFFFFFFFu;
        else if (V <= b0)      word = 0u;
        else                   word = (1u << (V - b0)) - 1u;
        s->keep32[wI] = word;
    }
    __syncthreads();

    // ---- 5. chunked greedy NMS: 32 boxes per round ----
    const int nchunks = (V + 31) >> 5;
    for (int c = 0; c < nchunks; c++) {
        unsigned int w = s->keep32[c];       // word c is never written during round c
        if (w != 0u) {
            const int b0 = c << 5;
            // every warp redundantly resolves the chunk (warp-local, no block sync)
            int myi = b0 + lane; if (myi > NBOX - 1) myi = NBOX - 1;
            float4 myb = s->boxes[myi];
            unsigned int sup = 0u;           // bit i set: box b0+i suppresses my box
#pragma unroll 4
            for (int i = 0; i < 32; i++) {
                int bi = b0 + i; if (bi > NBOX - 1) bi = NBOX - 1;
                float4 bo = s->boxes[bi];
                bool su = (i < lane) && (iou_f(bo, myb) > 0.5f);
                sup |= ((unsigned int)su) << i;
            }
            unsigned int alive = w;
            for (int i = 0; i < 32; i++) {
                if ((alive >> i) & 1u) {
                    unsigned int bal = __ballot_sync(0xFFFFFFFFu, (sup >> i) & 1u);
                    alive &= ~bal;
                }
            }
            if (tid == 0) s->final32[c] = alive;

            // suppress later boxes against this chunk's survivors
            for (int j = b0 + 32 + tid; j < V; j += NT) {
                float4 bj = s->boxes[j];
                bool supd = false;
                unsigned int m = alive;
                while (m && !supd) {
                    int i = __ffs(m) - 1; m &= m - 1;
                    if (iou_f(s->boxes[b0 + i], bj) > 0.5f) supd = true;
                }
                if (supd) atomicAnd(&s->keep32[j >> 5], ~(1u << (j & 31)));
            }
        } else {
            if (tid == 0) s->final32[c] = 0u;
        }
        __syncthreads();
    }

    // ---- 6. output: fully coalesced flat writes ----
    const float* boxesf = reinterpret_cast<const float*>(s->boxes);
#pragma unroll
    for (int m = 0; m < 5 * EPT; m++) {
        int f = tid + m * NT;                 // flat index into [8192,5]
        int i = f / 5;
        int comp = f - i * 5;
        bool kept = (i < V) && ((s->final32[i >> 5] >> (i & 31)) & 1u);
        float val = 0.0f;
        if (kept) {
            if (comp == 4) {
                float cconf = __uint_as_float((unsigned int)(s->keys[i] >> 32));
                val = cconf / maxv;
            } else {
                val = boxesf[i * 4 + comp];
            }
        }
        out[f] = val;
    }
}

extern "C" void kernel_launch(void* const* d_in, const int* in_sizes, int n_in,
                              void* d_out, int out_size)
{
    (void)in_sizes; (void)n_in; (void)out_size;
    const float* in = (const float*)d_in[0];
    float* out = (float*)d_out;

    const int smem_bytes = (int)sizeof(SmemLayout);
    cudaFuncSetAttribute(rtdetr_postprocess_kernel,
                         cudaFuncAttributeMaxDynamicSharedMemorySize, smem_bytes);
    rtdetr_postprocess_kernel<<<1, NT, smem_bytes>>>(in, out);
}

// round 7
// speedup vs baseline: 2.0378x; 2.0378x over previous
#include <cuda_runtime.h>

#define NBOX   8192
#define NT     1024
#define EPT    8                 // elements per thread in sort kernel
#define MAXW   256               // max words per suppression row (8192/32)

// ---- device globals (allocation-free scratch) ----
__device__ float4        g_boxes[NBOX];            // sorted xyxy, i < V
__device__ float         g_score[NBOX];            // sorted normalized score, i < V
__device__ int           g_V;
__device__ unsigned int  g_mat[NBOX * MAXW];       // 8MB suppression bit matrix (upper triangle only ever written)

struct SortSmem {
    unsigned long long keys[NBOX];
    float              redbuf[32];
    float              maxv;
    int                V;
};

__device__ __forceinline__ unsigned long long u64max(unsigned long long a, unsigned long long b) { return a > b ? a : b; }
__device__ __forceinline__ unsigned long long u64min(unsigned long long a, unsigned long long b) { return a < b ? a : b; }

__device__ __forceinline__ void local_stage(unsigned long long v[EPT], int base, int k, int j)
{
    if (j < EPT) {
#pragma unroll
        for (int r = 0; r < EPT; r++) {
            if ((r & j) == 0) {
                int r2 = r | j;
                bool dir = (((base + r) & k) == 0);
                unsigned long long a = v[r], b = v[r2];
                bool sw = dir ? (a < b) : (a > b);
                if (sw) { v[r] = b; v[r2] = a; }
            }
        }
    } else {
        int m = j >> 3;
#pragma unroll
        for (int r = 0; r < EPT; r++) {
            unsigned long long p = __shfl_xor_sync(0xFFFFFFFFu, v[r], m);
            int e = base + r;
            bool dir   = ((e & k) == 0);
            bool lower = ((e & j) == 0);
            unsigned long long a = v[r];
            v[r] = (dir == lower) ? u64max(a, p) : u64min(a, p);
        }
    }
}

__device__ __forceinline__ float iou_f(float4 a, float4 b)
{
    float ix1 = fmaxf(a.x, b.x);
    float iy1 = fmaxf(a.y, b.y);
    float ix2 = fminf(a.z, b.z);
    float iy2 = fminf(a.w, b.w);
    float iw  = fmaxf(ix2 - ix1, 0.0f);
    float ih  = fmaxf(iy2 - iy1, 0.0f);
    float inter = iw * ih;
    float areaA = (a.z - a.x) * (a.w - a.y);
    float areaB = (b.z - b.x) * (b.w - b.y);
    float uni   = areaA + areaB - inter;
    return inter / fmaxf(uni, 1e-9f);
}

// ================= K1: max + sort + gather to globals (1 block) =================
__global__ void __launch_bounds__(NT, 1)
k1_sort_kernel(const float* __restrict__ in)
{
    extern __shared__ unsigned char smem_raw[];
    SortSmem* s = reinterpret_cast<SortSmem*>(smem_raw);
    const int tid  = (int)threadIdx.x;
    const int lane = tid & 31;
    const int base = tid * EPT;

    if (tid == 0) s->V = 0;

    unsigned long long v[EPT];
    float lmax = 0.0f;
#pragma unroll
    for (int r = 0; r < EPT; r++) {
        int i = base + r;
        float c = in[i * 5 + 4];
        lmax = fmaxf(lmax, c);
        unsigned int cb = __float_as_uint(c);
        v[r] = ((unsigned long long)cb << 32) | (unsigned int)(0xFFFFFFFFu - (unsigned int)i);
    }
#pragma unroll
    for (int o = 16; o > 0; o >>= 1) lmax = fmaxf(lmax, __shfl_xor_sync(0xFFFFFFFFu, lmax, o));
    if (lane == 0) s->redbuf[tid >> 5] = lmax;

    for (int k = 2; k <= 256; k <<= 1)
        for (int j = k >> 1; j >= 1; j >>= 1)
            local_stage(v, base, k, j);

#pragma unroll
    for (int r = 0; r < EPT; r++) s->keys[base + r] = v[r];
    __syncthreads();

    if (tid < 32) {
        float m = s->redbuf[tid];
#pragma unroll
        for (int o = 16; o > 0; o >>= 1) m = fmaxf(m, __shfl_xor_sync(0xFFFFFFFFu, m, o));
        if (tid == 0) s->maxv = m;
    }

    for (int k = 512; k <= NBOX; k <<= 1) {
        for (int j = k >> 1; j >= 256; j >>= 1) {
#pragma unroll
            for (int r = 0; r < EPT; r++) {
                int i = tid + (r << 10);
                int ixj = i ^ j;
                if (ixj > i) {
                    unsigned long long a = s->keys[i];
                    unsigned long long b = s->keys[ixj];
                    bool desc = ((i & k) == 0);
                    if (desc ? (a < b) : (a > b)) { s->keys[i] = b; s->keys[ixj] = a; }
                }
            }
            __syncthreads();
        }
#pragma unroll
        for (int r = 0; r < EPT; r++) v[r] = s->keys[base + r];
        for (int j = 128; j >= 1; j >>= 1) local_stage(v, base, k, j);
#pragma unroll
        for (int r = 0; r < EPT; r++) s->keys[base + r] = v[r];
        __syncthreads();
    }

    // V = count of valid (valid is a sorted prefix)
    const float maxv = s->maxv;
    int cnt = 0;
#pragma unroll
    for (int r = 0; r < EPT; r++) {
        float c = __uint_as_float((unsigned int)(v[r] >> 32));
        cnt += ((c / maxv) >= 0.5f) ? 1 : 0;
    }
#pragma unroll
    for (int o = 16; o > 0; o >>= 1) cnt += __shfl_xor_sync(0xFFFFFFFFu, cnt, o);
    if (lane == 0) atomicAdd(&s->V, cnt);
    __syncthreads();
    const int V = s->V;

    // gather sorted boxes + scores to global
    for (int i = tid; i < V; i += NT) {
        unsigned long long key = s->keys[i];
        unsigned int idx = 0xFFFFFFFFu - (unsigned int)(key & 0xFFFFFFFFull);
        const float* p = in + (size_t)idx * 5;
        float cx = p[0], cy = p[1], w = p[2], h = p[3];
        g_boxes[i] = make_float4(cx - w * 0.5f, cy - h * 0.5f,
                                 cx + w * 0.5f, cy + h * 0.5f);
        g_score[i] = __uint_as_float((unsigned int)(key >> 32)) / maxv;
    }
    if (tid == 0) g_V = V;
}

// ================= K2: suppression bit matrix (multi-SM) =================
#define K2_ROWS 32
#define K2_NT   256
__global__ void __launch_bounds__(K2_NT)
k2_matrix_kernel()
{
    __shared__ float4 sbox[K2_ROWS];
    const int V  = g_V;
    const int nw = (V + 31) >> 5;
    const int row0 = blockIdx.x * K2_ROWS;
    if (row0 >= V) return;

    if (threadIdx.x < K2_ROWS && row0 + threadIdx.x < V)
        sbox[threadIdx.x] = g_boxes[row0 + threadIdx.x];
    __syncthreads();

    const int warp = threadIdx.x >> 5;
    const int lane = threadIdx.x & 31;

    for (int rr = warp; rr < K2_ROWS; rr += K2_NT / 32) {
        int i = row0 + rr;
        if (i >= V) break;
        float4 bi = sbox[rr];
        int c0 = i >> 5;                       // first word that can contain j > i
        for (int c = c0; c < nw; c++) {
            int j = (c << 5) + lane;
            bool su = false;
            if (j > i && j < V) {
                float4 bj = g_boxes[j];
                su = iou_f(bi, bj) > 0.5f;
            }
            unsigned int word = __ballot_sync(0xFFFFFFFFu, su);
            if (lane == 0) g_mat[i * MAXW + c] = word;
        }
    }
}

// ================= K3: serial greedy sweep (1 warp) + output =================
__global__ void __launch_bounds__(NT, 1)
k3_reduce_out_kernel(float* __restrict__ out)
{
    __shared__ unsigned int s_remv[MAXW];
    const int V  = g_V;
    const int nw = (V + 31) >> 5;
    const int tid = (int)threadIdx.x;

    if (tid < 32) {
        const int lane = tid;
        // lane owns words [8*lane, 8*lane+8) as two uint4
        uint4 rA = make_uint4(0u, 0u, 0u, 0u);
        uint4 rB = make_uint4(0u, 0u, 0u, 0u);
        const bool lactive = (8 * lane) < nw;

        for (int w = 0; w < nw; w++) {
            // broadcast remv word w from its owner lane (uniform switch, shfl)
            unsigned int vsel;
            switch (w & 7) {
                case 0: vsel = rA.x; break;
                case 1: vsel = rA.y; break;
                case 2: vsel = rA.z; break;
                case 3: vsel = rA.w; break;
                case 4: vsel = rB.x; break;
                case 5: vsel = rB.y; break;
                case 6: vsel = rB.z; break;
                default: vsel = rB.w; break;
            }
            unsigned int curw = __shfl_sync(0xFFFFFFFFu, vsel, w >> 3);

            int i_end = min(V, (w << 5) + 32);
            for (int i = (w << 5); i < i_end; i++) {
                const uint4* rowp = reinterpret_cast<const uint4*>(g_mat + (size_t)i * MAXW);
                uint4 ra, rb;
                if (lactive) { ra = rowp[2 * lane]; rb = rowp[2 * lane + 1]; }
                unsigned int rw = g_mat[i * MAXW + w];   // uniform-address broadcast load
                bool kept = ((curw >> (i & 31)) & 1u) == 0u;
                if (kept) {
                    if (lactive) {
                        rA.x |= ra.x; rA.y |= ra.y; rA.z |= ra.z; rA.w |= ra.w;
                        rB.x |= rb.x; rB.y |= rb.y; rB.z |= rb.z; rB.w |= rb.w;
                    }
                    curw |= rw;    // row i's bits for later boxes in this same word
                }
            }
        }
        // publish remv to smem
        if (lactive) {
            int b0 = 8 * lane;
            s_remv[b0 + 0] = rA.x; s_remv[b0 + 1] = rA.y;
            s_remv[b0 + 2] = rA.z; s_remv[b0 + 3] = rA.w;
            s_remv[b0 + 4] = rB.x; s_remv[b0 + 5] = rB.y;
            s_remv[b0 + 6] = rB.z; s_remv[b0 + 7] = rB.w;
        }
    } else {
        // warps 1..31: zero the whole output concurrently with the sweep
        float4* o4 = reinterpret_cast<float4*>(out);
        const float4 z = make_float4(0.f, 0.f, 0.f, 0.f);
        for (int f = tid - 32; f < (NBOX * 5) / 4; f += NT - 32) o4[f] = z;
    }
    __syncthreads();

    // write kept rows
    for (int i = tid; i < V; i += NT) {
        bool kept = ((s_remv[i >> 5] >> (i & 31)) & 1u) == 0u;
        if (kept) {
            float4 b = g_boxes[i];
            out[i * 5 + 0] = b.x;
            out[i * 5 + 1] = b.y;
            out[i * 5 + 2] = b.z;
            out[i * 5 + 3] = b.w;
            out[i * 5 + 4] = g_score[i];
        }
    }
}

extern "C" void kernel_launch(void* const* d_in, const int* in_sizes, int n_in,
                              void* d_out, int out_size)
{
    (void)in_sizes; (void)n_in; (void)out_size;
    const float* in = (const float*)d_in[0];
    float* out = (float*)d_out;

    const int smem_bytes = (int)sizeof(SortSmem);
    cudaFuncSetAttribute(k1_sort_kernel,
                         cudaFuncAttributeMaxDynamicSharedMemorySize, smem_bytes);

    k1_sort_kernel<<<1, NT, smem_bytes>>>(in);
    k2_matrix_kernel<<<NBOX / K2_ROWS, K2_NT>>>();
    k3_reduce_out_kernel<<<1, NT>>>(out);
}

// round 8
// speedup vs baseline: 4.0324x; 1.9788x over previous
#include <cuda_runtime.h>

#define NBOX   8192
#define NT     1024
#define EPT    8                 // elements per thread in sort kernel
#define MAXW   256               // words per suppression row (8192/32)

// ---- device globals (allocation-free scratch) ----
__device__ float4        g_boxes[NBOX];            // sorted xyxy, i < V
__device__ float         g_score[NBOX];            // sorted normalized score, i < V
__device__ int           g_V;
__device__ unsigned int  g_mat[NBOX * MAXW];       // 8MB suppression bit matrix (upper triangle only ever written)

struct SortSmem {
    unsigned long long keys[NBOX];
    float              redbuf[32];
    float              maxv;
    int                V;
};

__device__ __forceinline__ unsigned long long u64max(unsigned long long a, unsigned long long b) { return a > b ? a : b; }
__device__ __forceinline__ unsigned long long u64min(unsigned long long a, unsigned long long b) { return a < b ? a : b; }

__device__ __forceinline__ void local_stage(unsigned long long v[EPT], int base, int k, int j)
{
    if (j < EPT) {
#pragma unroll
        for (int r = 0; r < EPT; r++) {
            if ((r & j) == 0) {
                int r2 = r | j;
                bool dir = (((base + r) & k) == 0);
                unsigned long long a = v[r], b = v[r2];
                bool sw = dir ? (a < b) : (a > b);
                if (sw) { v[r] = b; v[r2] = a; }
            }
        }
    } else {
        int m = j >> 3;
#pragma unroll
        for (int r = 0; r < EPT; r++) {
            unsigned long long p = __shfl_xor_sync(0xFFFFFFFFu, v[r], m);
            int e = base + r;
            bool dir   = ((e & k) == 0);
            bool lower = ((e & j) == 0);
            unsigned long long a = v[r];
            v[r] = (dir == lower) ? u64max(a, p) : u64min(a, p);
        }
    }
}

__device__ __forceinline__ float iou_f(float4 a, float4 b)
{
    float ix1 = fmaxf(a.x, b.x);
    float iy1 = fmaxf(a.y, b.y);
    float ix2 = fminf(a.z, b.z);
    float iy2 = fminf(a.w, b.w);
    float iw  = fmaxf(ix2 - ix1, 0.0f);
    float ih  = fmaxf(iy2 - iy1, 0.0f);
    float inter = iw * ih;
    float areaA = (a.z - a.x) * (a.w - a.y);
    float areaB = (b.z - b.x) * (b.w - b.y);
    float uni   = areaA + areaB - inter;
    return inter / fmaxf(uni, 1e-9f);
}

// ================= K1: max + sort + gather to globals (1 block) =================
__global__ void __launch_bounds__(NT, 1)
k1_sort_kernel(const float* __restrict__ in)
{
    extern __shared__ unsigned char smem_raw[];
    SortSmem* s = reinterpret_cast<SortSmem*>(smem_raw);
    const int tid  = (int)threadIdx.x;
    const int lane = tid & 31;
    const int base = tid * EPT;

    if (tid == 0) s->V = 0;

    unsigned long long v[EPT];
    float lmax = 0.0f;
#pragma unroll
    for (int r = 0; r < EPT; r++) {
        int i = base + r;
        float c = in[i * 5 + 4];
        lmax = fmaxf(lmax, c);
        unsigned int cb = __float_as_uint(c);
        v[r] = ((unsigned long long)cb << 32) | (unsigned int)(0xFFFFFFFFu - (unsigned int)i);
    }
#pragma unroll
    for (int o = 16; o > 0; o >>= 1) lmax = fmaxf(lmax, __shfl_xor_sync(0xFFFFFFFFu, lmax, o));
    if (lane == 0) s->redbuf[tid >> 5] = lmax;

    for (int k = 2; k <= 256; k <<= 1)
        for (int j = k >> 1; j >= 1; j >>= 1)
            local_stage(v, base, k, j);

#pragma unroll
    for (int r = 0; r < EPT; r++) s->keys[base + r] = v[r];
    __syncthreads();

    if (tid < 32) {
        float m = s->redbuf[tid];
#pragma unroll
        for (int o = 16; o > 0; o >>= 1) m = fmaxf(m, __shfl_xor_sync(0xFFFFFFFFu, m, o));
        if (tid == 0) s->maxv = m;
    }

    for (int k = 512; k <= NBOX; k <<= 1) {
        for (int j = k >> 1; j >= 256; j >>= 1) {
#pragma unroll
            for (int r = 0; r < EPT; r++) {
                int i = tid + (r << 10);
                int ixj = i ^ j;
                if (ixj > i) {
                    unsigned long long a = s->keys[i];
                    unsigned long long b = s->keys[ixj];
                    bool desc = ((i & k) == 0);
                    if (desc ? (a < b) : (a > b)) { s->keys[i] = b; s->keys[ixj] = a; }
                }
            }
            __syncthreads();
        }
#pragma unroll
        for (int r = 0; r < EPT; r++) v[r] = s->keys[base + r];
        for (int j = 128; j >= 1; j >>= 1) local_stage(v, base, k, j);
#pragma unroll
        for (int r = 0; r < EPT; r++) s->keys[base + r] = v[r];
        __syncthreads();
    }

    // V = count of valid (valid is a sorted prefix)
    const float maxv = s->maxv;
    int cnt = 0;
#pragma unroll
    for (int r = 0; r < EPT; r++) {
        float c = __uint_as_float((unsigned int)(v[r] >> 32));
        cnt += ((c / maxv) >= 0.5f) ? 1 : 0;
    }
#pragma unroll
    for (int o = 16; o > 0; o >>= 1) cnt += __shfl_xor_sync(0xFFFFFFFFu, cnt, o);
    if (lane == 0) atomicAdd(&s->V, cnt);
    __syncthreads();
    const int V = s->V;

    // gather sorted boxes + scores to global
    for (int i = tid; i < V; i += NT) {
        unsigned long long key = s->keys[i];
        unsigned int idx = 0xFFFFFFFFu - (unsigned int)(key & 0xFFFFFFFFull);
        const float* p = in + (size_t)idx * 5;
        float cx = p[0], cy = p[1], w = p[2], h = p[3];
        g_boxes[i] = make_float4(cx - w * 0.5f, cy - h * 0.5f,
                                 cx + w * 0.5f, cy + h * 0.5f);
        g_score[i] = __uint_as_float((unsigned int)(key >> 32)) / maxv;
    }
    if (tid == 0) g_V = V;
}

// ================= K2: suppression bit matrix (multi-SM) =================
#define K2_ROWS 32
#define K2_NT   256
__global__ void __launch_bounds__(K2_NT)
k2_matrix_kernel()
{
    __shared__ float4 sbox[K2_ROWS];
    const int V  = g_V;
    const int nw = (V + 31) >> 5;
    const int row0 = blockIdx.x * K2_ROWS;
    if (row0 >= V) return;

    if (threadIdx.x < K2_ROWS && row0 + threadIdx.x < V)
        sbox[threadIdx.x] = g_boxes[row0 + threadIdx.x];
    __syncthreads();

    const int warp = threadIdx.x >> 5;
    const int lane = threadIdx.x & 31;

    for (int rr = warp; rr < K2_ROWS; rr += K2_NT / 32) {
        int i = row0 + rr;
        if (i >= V) break;
        float4 bi = sbox[rr];
        int c0 = i >> 5;                       // first word that can contain j > i
        for (int c = c0; c < nw; c++) {
            int j = (c << 5) + lane;
            bool su = false;
            if (j > i && j < V) {
                float4 bj = g_boxes[j];
                su = iou_f(bi, bj) > 0.5f;
            }
            unsigned int word = __ballot_sync(0xFFFFFFFFu, su);
            if (lane == 0) g_mat[i * MAXW + c] = word;
        }
    }
}

// ================= K3: greedy sweep, diagonal-prefetched (1 warp) + output =================
__global__ void __launch_bounds__(NT, 1)
k3_reduce_out_kernel(float* __restrict__ out)
{
    __shared__ unsigned int s_remv[MAXW];
    const int V  = g_V;
    const int nw = (V + 31) >> 5;
    const int tid = (int)threadIdx.x;

    if (tid < 32) {
        const int lane = tid;
        // lane owns remv words [8*lane, 8*lane+8) as two uint4 accumulators
        uint4 rA = make_uint4(0u, 0u, 0u, 0u);
        uint4 rB = make_uint4(0u, 0u, 0u, 0u);

        for (int w = 0; w < nw; w++) {
            const int ibase = w << 5;

            // parallel prefetch of the diagonal column: dcol[lane] = mat[ibase+lane][w]
            int di = ibase + lane;
            unsigned int dcol = (di < V) ? g_mat[(size_t)di * MAXW + w] : 0u;

            // current remv word w, broadcast from its owner lane
            unsigned int vsel;
            switch (w & 7) {
                case 0: vsel = rA.x; break;
                case 1: vsel = rA.y; break;
                case 2: vsel = rA.z; break;
                case 3: vsel = rA.w; break;
                case 4: vsel = rB.x; break;
                case 5: vsel = rB.y; break;
                case 6: vsel = rB.z; break;
                default: vsel = rB.w; break;
            }
            unsigned int curw = __shfl_sync(0xFFFFFFFFu, vsel, w >> 3);

            const int i_cnt = min(V - ibase, 32);
            for (int il = 0; il < i_cnt; il++) {
                const int i = ibase + il;
                // unconditional, statically-addressed row loads (pipeline freely)
                const uint4* rowp = reinterpret_cast<const uint4*>(g_mat + (size_t)i * MAXW);
                uint4 ra = rowp[2 * lane];
                uint4 rb = rowp[2 * lane + 1];
                // serial chain is register-only: shfl + OR
                unsigned int rw = __shfl_sync(0xFFFFFFFFu, dcol, il);
                unsigned int km = (((curw >> il) & 1u) == 0u) ? 0xFFFFFFFFu : 0u;
                rA.x |= ra.x & km; rA.y |= ra.y & km; rA.z |= ra.z & km; rA.w |= ra.w & km;
                rB.x |= rb.x & km; rB.y |= rb.y & km; rB.z |= rb.z & km; rB.w |= rb.w & km;
                curw |= rw & km;
            }
            // no write-back needed: owner lane's accumulator received the identical
            // word-w bits through the full-row ORs (matrix is strictly upper-triangular)
        }

        int b0 = 8 * lane;
        s_remv[b0 + 0] = rA.x; s_remv[b0 + 1] = rA.y;
        s_remv[b0 + 2] = rA.z; s_remv[b0 + 3] = rA.w;
        s_remv[b0 + 4] = rB.x; s_remv[b0 + 5] = rB.y;
        s_remv[b0 + 6] = rB.z; s_remv[b0 + 7] = rB.w;
    } else {
        // warps 1..31: zero the whole output concurrently with the sweep
        float4* o4 = reinterpret_cast<float4*>(out);
        const float4 z = make_float4(0.f, 0.f, 0.f, 0.f);
        for (int f = tid - 32; f < (NBOX * 5) / 4; f += NT - 32) o4[f] = z;
    }
    __syncthreads();

    // write kept rows
    for (int i = tid; i < V; i += NT) {
        bool kept = ((s_remv[i >> 5] >> (i & 31)) & 1u) == 0u;
        if (kept) {
            float4 b = g_boxes[i];
            out[i * 5 + 0] = b.x;
            out[i * 5 + 1] = b.y;
            out[i * 5 + 2] = b.z;
            out[i * 5 + 3] = b.w;
            out[i * 5 + 4] = g_score[i];
        }
    }
}

extern "C" void kernel_launch(void* const* d_in, const int* in_sizes, int n_in,
                              void* d_out, int out_size)
{
    (void)in_sizes; (void)n_in; (void)out_size;
    const float* in = (const float*)d_in[0];
    float* out = (float*)d_out;

    const int smem_bytes = (int)sizeof(SortSmem);
    cudaFuncSetAttribute(k1_sort_kernel,
                         cudaFuncAttributeMaxDynamicSharedMemorySize, smem_bytes);

    k1_sort_kernel<<<1, NT, smem_bytes>>>(in);
    k2_matrix_kernel<<<NBOX / K2_ROWS, K2_NT>>>();
    k3_reduce_out_kernel<<<1, NT>>>(out);
}

// round 9
// speedup vs baseline: 7.5839x; 1.8807x over previous
#include <cuda_runtime.h>

#define NBOX   8192
#define NT     1024
#define EPT    8                 // elements per thread in sort kernel
#define MAXW   256               // words per suppression row (8192/32)

// ---- device globals (allocation-free scratch) ----
__device__ float4        g_boxes[NBOX];            // sorted xyxy, i < V
__device__ float         g_score[NBOX];            // sorted normalized score, i < V
__device__ int           g_V;
__device__ unsigned int  g_mat[NBOX * MAXW];       // 8MB suppression bit matrix (upper triangle only ever written)

struct SortSmem {
    unsigned long long keys[NBOX];
    float              redbuf[32];
    float              maxv;
    int                V;
};

__device__ __forceinline__ unsigned long long u64max(unsigned long long a, unsigned long long b) { return a > b ? a : b; }
__device__ __forceinline__ unsigned long long u64min(unsigned long long a, unsigned long long b) { return a < b ? a : b; }

__device__ __forceinline__ void local_stage(unsigned long long v[EPT], int base, int k, int j)
{
    if (j < EPT) {
#pragma unroll
        for (int r = 0; r < EPT; r++) {
            if ((r & j) == 0) {
                int r2 = r | j;
                bool dir = (((base + r) & k) == 0);
                unsigned long long a = v[r], b = v[r2];
                bool sw = dir ? (a < b) : (a > b);
                if (sw) { v[r] = b; v[r2] = a; }
            }
        }
    } else {
        int m = j >> 3;
#pragma unroll
        for (int r = 0; r < EPT; r++) {
            unsigned long long p = __shfl_xor_sync(0xFFFFFFFFu, v[r], m);
            int e = base + r;
            bool dir   = ((e & k) == 0);
            bool lower = ((e & j) == 0);
            unsigned long long a = v[r];
            v[r] = (dir == lower) ? u64max(a, p) : u64min(a, p);
        }
    }
}

__device__ __forceinline__ float iou_f(float4 a, float4 b)
{
    float ix1 = fmaxf(a.x, b.x);
    float iy1 = fmaxf(a.y, b.y);
    float ix2 = fminf(a.z, b.z);
    float iy2 = fminf(a.w, b.w);
    float iw  = fmaxf(ix2 - ix1, 0.0f);
    float ih  = fmaxf(iy2 - iy1, 0.0f);
    float inter = iw * ih;
    float areaA = (a.z - a.x) * (a.w - a.y);
    float areaB = (b.z - b.x) * (b.w - b.y);
    float uni   = areaA + areaB - inter;
    return inter / fmaxf(uni, 1e-9f);
}

// ================= K1: max + sort + gather to globals (1 block) =================
__global__ void __launch_bounds__(NT, 1)
k1_sort_kernel(const float* __restrict__ in)
{
    extern __shared__ unsigned char smem_raw[];
    SortSmem* s = reinterpret_cast<SortSmem*>(smem_raw);
    const int tid  = (int)threadIdx.x;
    const int lane = tid & 31;
    const int base = tid * EPT;

    if (tid == 0) s->V = 0;

    unsigned long long v[EPT];
    float lmax = 0.0f;
#pragma unroll
    for (int r = 0; r < EPT; r++) {
        int i = base + r;
        float c = in[i * 5 + 4];
        lmax = fmaxf(lmax, c);
        unsigned int cb = __float_as_uint(c);
        v[r] = ((unsigned long long)cb << 32) | (unsigned int)(0xFFFFFFFFu - (unsigned int)i);
    }
#pragma unroll
    for (int o = 16; o > 0; o >>= 1) lmax = fmaxf(lmax, __shfl_xor_sync(0xFFFFFFFFu, lmax, o));
    if (lane == 0) s->redbuf[tid >> 5] = lmax;

    for (int k = 2; k <= 256; k <<= 1)
        for (int j = k >> 1; j >= 1; j >>= 1)
            local_stage(v, base, k, j);

#pragma unroll
    for (int r = 0; r < EPT; r++) s->keys[base + r] = v[r];
    __syncthreads();

    if (tid < 32) {
        float m = s->redbuf[tid];
#pragma unroll
        for (int o = 16; o > 0; o >>= 1) m = fmaxf(m, __shfl_xor_sync(0xFFFFFFFFu, m, o));
        if (tid == 0) s->maxv = m;
    }

    for (int k = 512; k <= NBOX; k <<= 1) {
        for (int j = k >> 1; j >= 256; j >>= 1) {
#pragma unroll
            for (int r = 0; r < EPT; r++) {
                int i = tid + (r << 10);
                int ixj = i ^ j;
                if (ixj > i) {
                    unsigned long long a = s->keys[i];
                    unsigned long long b = s->keys[ixj];
                    bool desc = ((i & k) == 0);
                    if (desc ? (a < b) : (a > b)) { s->keys[i] = b; s->keys[ixj] = a; }
                }
            }
            __syncthreads();
        }
#pragma unroll
        for (int r = 0; r < EPT; r++) v[r] = s->keys[base + r];
        for (int j = 128; j >= 1; j >>= 1) local_stage(v, base, k, j);
#pragma unroll
        for (int r = 0; r < EPT; r++) s->keys[base + r] = v[r];
        __syncthreads();
    }

    // V = count of valid (valid is a sorted prefix)
    const float maxv = s->maxv;
    int cnt = 0;
#pragma unroll
    for (int r = 0; r < EPT; r++) {
        float c = __uint_as_float((unsigned int)(v[r] >> 32));
        cnt += ((c / maxv) >= 0.5f) ? 1 : 0;
    }
#pragma unroll
    for (int o = 16; o > 0; o >>= 1) cnt += __shfl_xor_sync(0xFFFFFFFFu, cnt, o);
    if (lane == 0) atomicAdd(&s->V, cnt);
    __syncthreads();
    const int V = s->V;

    // gather sorted boxes + scores to global
    for (int i = tid; i < V; i += NT) {
        unsigned long long key = s->keys[i];
        unsigned int idx = 0xFFFFFFFFu - (unsigned int)(key & 0xFFFFFFFFull);
        const float* p = in + (size_t)idx * 5;
        float cx = p[0], cy = p[1], w = p[2], h = p[3];
        g_boxes[i] = make_float4(cx - w * 0.5f, cy - h * 0.5f,
                                 cx + w * 0.5f, cy + h * 0.5f);
        g_score[i] = __uint_as_float((unsigned int)(key >> 32)) / maxv;
    }
    if (tid == 0) g_V = V;
}

// ================= K2: suppression bit matrix (multi-SM) =================
#define K2_ROWS 32
#define K2_NT   256
__global__ void __launch_bounds__(K2_NT)
k2_matrix_kernel()
{
    __shared__ float4 sbox[K2_ROWS];
    const int V  = g_V;
    const int nw = (V + 31) >> 5;
    const int row0 = blockIdx.x * K2_ROWS;
    if (row0 >= V) return;

    if (threadIdx.x < K2_ROWS && row0 + threadIdx.x < V)
        sbox[threadIdx.x] = g_boxes[row0 + threadIdx.x];
    __syncthreads();

    const int warp = threadIdx.x >> 5;
    const int lane = threadIdx.x & 31;

    for (int rr = warp; rr < K2_ROWS; rr += K2_NT / 32) {
        int i = row0 + rr;
        if (i >= V) break;
        float4 bi = sbox[rr];
        int c0 = i >> 5;
        for (int c = c0; c < nw; c++) {
            int j = (c << 5) + lane;
            bool su = false;
            if (j > i && j < V) {
                float4 bj = g_boxes[j];
                su = iou_f(bi, bj) > 0.5f;
            }
            unsigned int word = __ballot_sync(0xFFFFFFFFu, su);
            if (lane == 0) g_mat[i * MAXW + c] = word;
        }
    }
}

// ================= K3: producer/consumer greedy sweep (1 block) + output =================
// smem: stage[2][32][MAXW] words (double-buffered chunk rows) + remv[MAXW]
#define STAGE_WORDS (32 * MAXW)     // words per buffer
__global__ void __launch_bounds__(NT, 1)
k3_reduce_out_kernel(float* __restrict__ out)
{
    extern __shared__ unsigned int sm[];
    unsigned int* stage  = sm;                        // 2 * STAGE_WORDS
    unsigned int* s_remv = sm + 2 * STAGE_WORDS;      // MAXW

    const int V   = g_V;
    const int nw  = (V + 31) >> 5;
    const int nchunks = nw;
    const int tid  = (int)threadIdx.x;
    const int warp = tid >> 5;
    const int lane = tid & 31;
    const int nc4  = (nw + 3) >> 2;                   // uint4s per staged row

    // sweeper's distributed remv accumulators (lane owns words):
    //  fast path (nw<=128): rA only, words 4*lane..4*lane+3
    //  full path: rA=words 8*lane..+3, rB=words 8*lane+4..+7
    uint4 rA = make_uint4(0u, 0u, 0u, 0u);
    uint4 rB = make_uint4(0u, 0u, 0u, 0u);
    const bool fast = (nw <= 128);

    for (int w = 0; w <= nchunks; w++) {
        // ---- producers: stage chunk w's rows into buffer (w&1) ----
        if (warp > 0 && w < nchunks) {
            unsigned int* dstbuf = stage + (w & 1) * STAGE_WORDS;
            for (int r = warp - 1; r < 32; r += 31) {
                int gi = (w << 5) + r;                 // < NBOX always (nchunks<=256)
                const uint4* src = reinterpret_cast<const uint4*>(g_mat + (size_t)gi * MAXW);
                uint4* dst = reinterpret_cast<uint4*>(dstbuf + r * MAXW);
                for (int c4 = lane; c4 < nc4; c4 += 32) dst[c4] = src[c4];
            }
        }
        // ---- sweeper: process chunk w-1 from buffer ((w-1)&1) ----
        if (warp == 0 && w >= 1) {
            const int cw = w - 1;
            const unsigned int* st = stage + (cw & 1) * STAGE_WORDS;

            // diagonal column: dcol[lane] = row(cw*32+lane) word cw
            unsigned int dcol = st[lane * MAXW + cw];

            // current remv word cw from owner lane
            unsigned int vsel;
            if (fast) {
                switch (cw & 3) {
                    case 0: vsel = rA.x; break;
                    case 1: vsel = rA.y; break;
                    case 2: vsel = rA.z; break;
                    default: vsel = rA.w; break;
                }
            } else {
                switch (cw & 7) {
                    case 0: vsel = rA.x; break;
                    case 1: vsel = rA.y; break;
                    case 2: vsel = rA.z; break;
                    case 3: vsel = rA.w; break;
                    case 4: vsel = rB.x; break;
                    case 5: vsel = rB.y; break;
                    case 6: vsel = rB.z; break;
                    default: vsel = rB.w; break;
                }
            }
            unsigned int curw = __shfl_sync(0xFFFFFFFFu, vsel, fast ? (cw >> 2) : (cw >> 3));

            if (fast) {
#pragma unroll 8
                for (int il = 0; il < 32; il++) {
                    const uint4* rp = reinterpret_cast<const uint4*>(st + il * MAXW);
                    uint4 ra = rp[lane];                        // words 4*lane..4*lane+3
                    unsigned int rw = __shfl_sync(0xFFFFFFFFu, dcol, il);
                    unsigned int km = ((curw >> il) & 1u) - 1u; // ~0 if kept, 0 if removed
                    rA.x |= ra.x & km; rA.y |= ra.y & km;
                    rA.z |= ra.z & km; rA.w |= ra.w & km;
                    curw |= rw & km;
                }
            } else {
#pragma unroll 4
                for (int il = 0; il < 32; il++) {
                    const uint4* rp = reinterpret_cast<const uint4*>(st + il * MAXW);
                    uint4 ra = rp[2 * lane];
                    uint4 rb = rp[2 * lane + 1];
                    unsigned int rw = __shfl_sync(0xFFFFFFFFu, dcol, il);
                    unsigned int km = ((curw >> il) & 1u) - 1u;
                    rA.x |= ra.x & km; rA.y |= ra.y & km; rA.z |= ra.z & km; rA.w |= ra.w & km;
                    rB.x |= rb.x & km; rB.y |= rb.y & km; rB.z |= rb.z & km; rB.w |= rb.w & km;
                    curw |= rw & km;
                }
            }
            // no write-back: owner lane's accumulator received word-cw bits via the
            // full-row ORs (matrix strictly upper-triangular; sub-diagonal words are 0)
        }
        __syncthreads();
    }

    // publish remv
    if (warp == 0) {
        if (fast) {
            int b0 = 4 * lane;
            s_remv[b0 + 0] = rA.x; s_remv[b0 + 1] = rA.y;
            s_remv[b0 + 2] = rA.z; s_remv[b0 + 3] = rA.w;
        } else {
            int b0 = 8 * lane;
            s_remv[b0 + 0] = rA.x; s_remv[b0 + 1] = rA.y;
            s_remv[b0 + 2] = rA.z; s_remv[b0 + 3] = rA.w;
            s_remv[b0 + 4] = rB.x; s_remv[b0 + 5] = rB.y;
            s_remv[b0 + 6] = rB.z; s_remv[b0 + 7] = rB.w;
        }
    }
    __syncthreads();

    // ---- flat coalesced output: zeros + kept rows ----
    const float* boxesf = reinterpret_cast<const float*>(g_boxes);
#pragma unroll
    for (int m = 0; m < 5 * EPT; m++) {
        int f = tid + m * NT;                 // flat index into [8192,5]
        int i = f / 5;
        int comp = f - i * 5;
        bool kept = (i < V) && (((s_remv[i >> 5] >> (i & 31)) & 1u) == 0u);
        float val = 0.0f;
        if (kept) val = (comp == 4) ? g_score[i] : boxesf[i * 4 + comp];
        out[f] = val;
    }
}

extern "C" void kernel_launch(void* const* d_in, const int* in_sizes, int n_in,
                              void* d_out, int out_size)
{
    (void)in_sizes; (void)n_in; (void)out_size;
    const float* in = (const float*)d_in[0];
    float* out = (float*)d_out;

    const int smem1 = (int)sizeof(SortSmem);
    cudaFuncSetAttribute(k1_sort_kernel,
                         cudaFuncAttributeMaxDynamicSharedMemorySize, smem1);

    const int smem3 = (int)((2 * STAGE_WORDS + MAXW) * sizeof(unsigned int));
    cudaFuncSetAttribute(k3_reduce_out_kernel,
                         cudaFuncAttributeMaxDynamicSharedMemorySize, smem3);

    k1_sort_kernel<<<1, NT, smem1>>>(in);
    k2_matrix_kernel<<<NBOX / K2_ROWS, K2_NT>>>();
    k3_reduce_out_kernel<<<1, NT, smem3>>>(out);
}

// round 10
// speedup vs baseline: 8.6401x; 1.1393x over previous
#include <cuda_runtime.h>

#define NBOX   8192
#define NT     1024
#define MAXW   256               // words per suppression row (8192/32)

// ---- device globals (allocation-free scratch) ----
__device__ float4        g_boxes[NBOX];            // sorted xyxy, i < V
__device__ float         g_score[NBOX];            // sorted normalized score, i < V
__device__ int           g_V;
__device__ unsigned int  g_mat[NBOX * MAXW];       // 8MB suppression bit matrix (upper triangle only ever written)

struct SortSmem {
    unsigned long long keys[NBOX];
    float              redbuf[32];
    float              maxv;
    int                cnt;
};

__device__ __forceinline__ unsigned long long u64max(unsigned long long a, unsigned long long b) { return a > b ? a : b; }
__device__ __forceinline__ unsigned long long u64min(unsigned long long a, unsigned long long b) { return a < b ? a : b; }

template<int EPTX>
__device__ __forceinline__ void local_stageT(unsigned long long v[EPTX], int base, int k, int j)
{
    if (j < EPTX) {
#pragma unroll
        for (int r = 0; r < EPTX; r++) {
            if ((r & j) == 0) {
                int r2 = r | j;
                bool dir = (((base + r) & k) == 0);
                unsigned long long a = v[r], b = v[r2];
                bool sw = dir ? (a < b) : (a > b);
                if (sw) { v[r] = b; v[r2] = a; }
            }
        }
    } else {
        int m = j / EPTX;                 // partner lane xor (warp owns 32*EPTX consecutive)
#pragma unroll
        for (int r = 0; r < EPTX; r++) {
            unsigned long long p = __shfl_xor_sync(0xFFFFFFFFu, v[r], m);
            int e = base + r;
            bool dir   = ((e & k) == 0);
            bool lower = ((e & j) == 0);
            unsigned long long a = v[r];
            v[r] = (dir == lower) ? u64max(a, p) : u64min(a, p);
        }
    }
}

// Hybrid bitonic sort (descending) of N = NT*EPTX elements resident in smem keys[].
template<int EPTX>
__device__ void sort_hybridT(unsigned long long* keys, int tid)
{
    const int N    = NT * EPTX;
    const int base = tid * EPTX;
    const int KREG = 32 * EPTX;           // largest k fully handled in registers/warp

    unsigned long long v[EPTX];
#pragma unroll
    for (int r = 0; r < EPTX; r++) v[r] = keys[base + r];

    for (int k = 2; k <= KREG; k <<= 1)
        for (int j = k >> 1; j >= 1; j >>= 1)
            local_stageT<EPTX>(v, base, k, j);

#pragma unroll
    for (int r = 0; r < EPTX; r++) keys[base + r] = v[r];
    __syncthreads();

    for (int k = KREG << 1; k <= N; k <<= 1) {
        for (int j = k >> 1; j >= KREG; j >>= 1) {
#pragma unroll
            for (int r = 0; r < EPTX; r++) {
                int i = tid + r * NT;
                int ixj = i ^ j;
                if (ixj > i) {
                    unsigned long long a = keys[i];
                    unsigned long long b = keys[ixj];
                    bool desc = ((i & k) == 0);
                    if (desc ? (a < b) : (a > b)) { keys[i] = b; keys[ixj] = a; }
                }
            }
            __syncthreads();
        }
#pragma unroll
        for (int r = 0; r < EPTX; r++) v[r] = keys[base + r];
        for (int j = KREG >> 1; j >= 1; j >>= 1) local_stageT<EPTX>(v, base, k, j);
#pragma unroll
        for (int r = 0; r < EPTX; r++) keys[base + r] = v[r];
        __syncthreads();
    }
}

__device__ __forceinline__ float iou_f(float4 a, float4 b)
{
    float ix1 = fmaxf(a.x, b.x);
    float iy1 = fmaxf(a.y, b.y);
    float ix2 = fminf(a.z, b.z);
    float iy2 = fminf(a.w, b.w);
    float iw  = fmaxf(ix2 - ix1, 0.0f);
    float ih  = fmaxf(iy2 - iy1, 0.0f);
    float inter = iw * ih;
    float areaA = (a.z - a.x) * (a.w - a.y);
    float areaB = (b.z - b.x) * (b.w - b.y);
    float uni   = areaA + areaB - inter;
    return inter / fmaxf(uni, 1e-9f);
}

// ================= K1: max + compact valid + sort + gather (1 block) =================
__global__ void __launch_bounds__(NT, 1)
k1_sort_kernel(const float* __restrict__ in)
{
    extern __shared__ unsigned char smem_raw[];
    SortSmem* s = reinterpret_cast<SortSmem*>(smem_raw);
    const int tid  = (int)threadIdx.x;
    const int lane = tid & 31;

    if (tid == 0) s->cnt = 0;

    // ---- max reduce ----
    float confs[8];
    float lmax = 0.0f;                    // conf >= 0 for this workload
#pragma unroll
    for (int r = 0; r < 8; r++) {
        int i = tid + r * NT;
        float c = in[i * 5 + 4];
        confs[r] = c;
        lmax = fmaxf(lmax, c);
    }
#pragma unroll
    for (int o = 16; o > 0; o >>= 1) lmax = fmaxf(lmax, __shfl_xor_sync(0xFFFFFFFFu, lmax, o));
    if (lane == 0) s->redbuf[tid >> 5] = lmax;
    __syncthreads();
    if (tid < 32) {
        float m = s->redbuf[tid];
#pragma unroll
        for (int o = 16; o > 0; o >>= 1) m = fmaxf(m, __shfl_xor_sync(0xFFFFFFFFu, m, o));
        if (tid == 0) s->maxv = m;
    }
    __syncthreads();
    const float maxv = s->maxv;

    // ---- compact valid entries (order-irrelevant; keys are unique) ----
#pragma unroll
    for (int r = 0; r < 8; r++) {
        int i = tid + r * NT;
        bool valid = (confs[r] / maxv) >= 0.5f;
        unsigned int bal = __ballot_sync(0xFFFFFFFFu, valid);
        int basep = 0;
        if (lane == 0) basep = atomicAdd(&s->cnt, __popc(bal));
        basep = __shfl_sync(0xFFFFFFFFu, basep, 0);
        if (valid) {
            int pos = basep + __popc(bal & ((1u << lane) - 1u));
            unsigned int cb = __float_as_uint(confs[r]);
            s->keys[pos] = ((unsigned long long)cb << 32) | (unsigned int)(0xFFFFFFFFu - (unsigned int)i);
        }
    }
    __syncthreads();
    const int count = s->cnt;
    const int npad  = (count <= 4096) ? 4096 : 8192;

    // pad with 0-keys (sink to tail under descending sort)
    for (int i = count + tid; i < npad; i += NT) s->keys[i] = 0ull;
    __syncthreads();

    if (npad == 4096) sort_hybridT<4>(s->keys, tid);
    else              sort_hybridT<8>(s->keys, tid);

    // ---- gather sorted boxes + scores to global ----
    for (int i = tid; i < count; i += NT) {
        unsigned long long key = s->keys[i];
        unsigned int idx = 0xFFFFFFFFu - (unsigned int)(key & 0xFFFFFFFFull);
        const float* p = in + (size_t)idx * 5;
        float cx = p[0], cy = p[1], w = p[2], h = p[3];
        g_boxes[i] = make_float4(cx - w * 0.5f, cy - h * 0.5f,
                                 cx + w * 0.5f, cy + h * 0.5f);
        g_score[i] = __uint_as_float((unsigned int)(key >> 32)) / maxv;
    }
    if (tid == 0) g_V = count;
}

// ================= K2: suppression bit matrix (multi-SM) =================
#define K2_ROWS 32
#define K2_NT   256
__global__ void __launch_bounds__(K2_NT)
k2_matrix_kernel()
{
    __shared__ float4 sbox[K2_ROWS];
    const int V  = g_V;
    const int nw = (V + 31) >> 5;
    const int row0 = blockIdx.x * K2_ROWS;
    if (row0 >= V) return;

    if (threadIdx.x < K2_ROWS && row0 + threadIdx.x < V)
        sbox[threadIdx.x] = g_boxes[row0 + threadIdx.x];
    __syncthreads();

    const int warp = threadIdx.x >> 5;
    const int lane = threadIdx.x & 31;

    for (int rr = warp; rr < K2_ROWS; rr += K2_NT / 32) {
        int i = row0 + rr;
        if (i >= V) break;
        float4 bi = sbox[rr];
        int c0 = i >> 5;
        for (int c = c0; c < nw; c++) {
            int j = (c << 5) + lane;
            bool su = false;
            if (j > i && j < V) {
                float4 bj = g_boxes[j];
                su = iou_f(bi, bj) > 0.5f;
            }
            unsigned int word = __ballot_sync(0xFFFFFFFFu, su);
            if (lane == 0) g_mat[i * MAXW + c] = word;
        }
    }
}

// ================= K3: producer/consumer greedy sweep (1 block) + output =================
#define STAGE_WORDS (32 * MAXW)
__global__ void __launch_bounds__(NT, 1)
k3_reduce_out_kernel(float* __restrict__ out)
{
    extern __shared__ unsigned int sm[];
    unsigned int* stage  = sm;                        // 2 * STAGE_WORDS
    unsigned int* s_diag = sm + 2 * STAGE_WORDS;      // 2 * 32
    unsigned int* s_remv = sm + 2 * STAGE_WORDS + 64; // MAXW

    const int V   = g_V;
    const int nw  = (V + 31) >> 5;
    const int nchunks = nw;
    const int tid  = (int)threadIdx.x;
    const int warp = tid >> 5;
    const int lane = tid & 31;
    const int nc4  = (nw + 3) >> 2;

    uint4 rA = make_uint4(0u, 0u, 0u, 0u);
    uint4 rB = make_uint4(0u, 0u, 0u, 0u);
    const bool fast = (nw <= 128);

    for (int w = 0; w <= nchunks; w++) {
        // ---- producers: stage chunk w rows into buffer (w&1), words >= w only ----
        if (warp > 0 && w < nchunks) {
            unsigned int* dstbuf = stage + (w & 1) * STAGE_WORDS;
            const int start4 = w >> 2;
            for (int r = warp - 1; r < 32; r += 31) {
                int gi = (w << 5) + r;
                const uint4* src = reinterpret_cast<const uint4*>(g_mat + (size_t)gi * MAXW);
                uint4* dst = reinterpret_cast<uint4*>(dstbuf + r * MAXW);
                for (int c4 = start4 + lane; c4 < nc4; c4 += 32) {
                    uint4 val = src[c4];
                    dst[c4] = val;
                    if (c4 == start4) {        // lane 0, first iter: deposit diagonal word w
                        unsigned int d;
                        switch (w & 3) {
                            case 0: d = val.x; break;
                            case 1: d = val.y; break;
                            case 2: d = val.z; break;
                            default: d = val.w; break;
                        }
                        s_diag[(w & 1) * 32 + r] = d;
                    }
                }
            }
        }
        // ---- sweeper: process chunk w-1 ----
        if (warp == 0 && w >= 1) {
            const int cw = w - 1;
            const unsigned int* st = stage + (cw & 1) * STAGE_WORDS;
            unsigned int dcol = s_diag[(cw & 1) * 32 + lane];   // conflict-free

            unsigned int vsel;
            if (fast) {
                switch (cw & 3) {
                    case 0: vsel = rA.x; break;
                    case 1: vsel = rA.y; break;
                    case 2: vsel = rA.z; break;
                    default: vsel = rA.w; break;
                }
            } else {
                switch (cw & 7) {
                    case 0: vsel = rA.x; break;
                    case 1: vsel = rA.y; break;
                    case 2: vsel = rA.z; break;
                    case 3: vsel = rA.w; break;
                    case 4: vsel = rB.x; break;
                    case 5: vsel = rB.y; break;
                    case 6: vsel = rB.z; break;
                    default: vsel = rB.w; break;
                }
            }
            unsigned int curw = __shfl_sync(0xFFFFFFFFu, vsel, fast ? (cw >> 2) : (cw >> 3));

            if (fast) {
                const bool act = (4 * lane + 3) >= cw;          // staged & nonzero region
#pragma unroll 8
                for (int il = 0; il < 32; il++) {
                    uint4 ra = make_uint4(0u, 0u, 0u, 0u);
                    if (act) ra = reinterpret_cast<const uint4*>(st + il * MAXW)[lane];
                    unsigned int rw = __shfl_sync(0xFFFFFFFFu, dcol, il);
                    unsigned int km = ((curw >> il) & 1u) - 1u; // ~0 kept, 0 removed
                    rA.x |= ra.x & km; rA.y |= ra.y & km;
                    rA.z |= ra.z & km; rA.w |= ra.w & km;
                    curw |= rw & km;
                }
            } else {
                const bool actA = (8 * lane + 3) >= cw;
                const bool actB = (8 * lane + 7) >= cw;
#pragma unroll 4
                for (int il = 0; il < 32; il++) {
                    const uint4* rp = reinterpret_cast<const uint4*>(st + il * MAXW);
                    uint4 ra = make_uint4(0u, 0u, 0u, 0u);
                    uint4 rb = make_uint4(0u, 0u, 0u, 0u);
                    if (actA) ra = rp[2 * lane];
                    if (actB) rb = rp[2 * lane + 1];
                    unsigned int rw = __shfl_sync(0xFFFFFFFFu, dcol, il);
                    unsigned int km = ((curw >> il) & 1u) - 1u;
                    rA.x |= ra.x & km; rA.y |= ra.y & km; rA.z |= ra.z & km; rA.w |= ra.w & km;
                    rB.x |= rb.x & km; rB.y |= rb.y & km; rB.z |= rb.z & km; rB.w |= rb.w & km;
                    curw |= rw & km;
                }
            }
            // no write-back: owner lane's accumulator got word-cw bits via the row ORs
        }
        __syncthreads();
    }

    // publish remv
    if (warp == 0) {
        if (fast) {
            int b0 = 4 * lane;
            s_remv[b0 + 0] = rA.x; s_remv[b0 + 1] = rA.y;
            s_remv[b0 + 2] = rA.z; s_remv[b0 + 3] = rA.w;
        } else {
            int b0 = 8 * lane;
            s_remv[b0 + 0] = rA.x; s_remv[b0 + 1] = rA.y;
            s_remv[b0 + 2] = rA.z; s_remv[b0 + 3] = rA.w;
            s_remv[b0 + 4] = rB.x; s_remv[b0 + 5] = rB.y;
            s_remv[b0 + 6] = rB.z; s_remv[b0 + 7] = rB.w;
        }
    }
    __syncthreads();

    // ---- flat coalesced output ----
    const float* boxesf = reinterpret_cast<const float*>(g_boxes);
#pragma unroll
    for (int m = 0; m < 40; m++) {
        int f = tid + m * NT;
        int i = f / 5;
        int comp = f - i * 5;
        bool kept = (i < V) && (((s_remv[i >> 5] >> (i & 31)) & 1u) == 0u);
        float val = 0.0f;
        if (kept) val = (comp == 4) ? g_score[i] : boxesf[i * 4 + comp];
        out[f] = val;
    }
}

extern "C" void kernel_launch(void* const* d_in, const int* in_sizes, int n_in,
                              void* d_out, int out_size)
{
    (void)in_sizes; (void)n_in; (void)out_size;
    const float* in = (const float*)d_in[0];
    float* out = (float*)d_out;

    const int smem1 = (int)sizeof(SortSmem);
    cudaFuncSetAttribute(k1_sort_kernel,
                         cudaFuncAttributeMaxDynamicSharedMemorySize, smem1);

    const int smem3 = (int)((2 * STAGE_WORDS + 64 + MAXW) * sizeof(unsigned int));
    cudaFuncSetAttribute(k3_reduce_out_kernel,
                         cudaFuncAttributeMaxDynamicSharedMemorySize, smem3);

    k1_sort_kernel<<<1, NT, smem1>>>(in);
    k2_matrix_kernel<<<NBOX / K2_ROWS, K2_NT>>>();
    k3_reduce_out_kernel<<<1, NT, smem3>>>(out);
}